// round 1
// baseline (speedup 1.0000x reference)
#include <cuda_runtime.h>
#include <cstdint>

#define CRF_B 512
#define CRF_S 1024
#define CRF_T 64

__device__ float g_partial[CRF_B];

__device__ __forceinline__ float ex2f(float x) {
    float r; asm("ex2.approx.f32 %0, %1;" : "=f"(r) : "f"(x)); return r;
}
__device__ __forceinline__ float lg2f(float x) {
    float r; asm("lg2.approx.f32 %0, %1;" : "=f"(r) : "f"(x)); return r;
}
__device__ __forceinline__ unsigned long long pack2(float lo, float hi) {
    unsigned long long r;
    unsigned lo_u = __float_as_uint(lo), hi_u = __float_as_uint(hi);
    asm("mov.b64 %0, {%1, %2};" : "=l"(r) : "r"(lo_u), "r"(hi_u));
    return r;
}
__device__ __forceinline__ void unpack2(unsigned long long v, float& lo, float& hi) {
    unsigned lo_u, hi_u;
    asm("mov.b64 {%0, %1}, %2;" : "=r"(lo_u), "=r"(hi_u) : "l"(v));
    lo = __uint_as_float(lo_u); hi = __uint_as_float(hi_u);
}
// Packed dual-FMA: d.lo = a.lo*b.lo + c.lo ; d.hi = a.hi*b.hi + c.hi
__device__ __forceinline__ unsigned long long ffma2(unsigned long long a,
                                                    unsigned long long b,
                                                    unsigned long long c) {
    unsigned long long d;
    asm("fma.rn.f32x2 %0, %1, %2, %3;" : "=l"(d) : "l"(a), "l"(b), "l"(c));
    return d;
}

__global__ __launch_bounds__(CRF_T)
void crf_main(const float* __restrict__ emis,
              const int*   __restrict__ tags,
              const float* __restrict__ mask,
              const float* __restrict__ trans)
{
    const int b    = blockIdx.x;
    const int j    = threadIdx.x;       // state index 0..63
    const int lane = j & 31;
    const int wid  = j >> 5;

    __shared__ __align__(16) float sE[CRF_T];
    __shared__ float sred[2];
    __shared__ float sAux[2];
    __shared__ float sGold;

    const float LOG2E = 1.4426950408889634f;
    const float LN2   = 0.6931471805599453f;

    const float* mb    = mask + (size_t)b * CRF_S;
    const int*   tb    = tags + (size_t)b * CRF_S;
    const float* ebase = emis + (size_t)b * CRF_S * CRF_T;

    // ---------------- Gold score (gather pass, split over threads) ----------
    float g = 0.f;
    for (int s = j; s < CRF_S; s += CRF_T) {
        int   tg = tb[s];
        float ev = ebase[(size_t)s * CRF_T + tg];
        float term;
        if (s == 0) term = ev;
        else        term = trans[tg * CRF_T + tb[s - 1]] + ev;
        g += term * mb[s];
    }
    #pragma unroll
    for (int off = 16; off; off >>= 1)
        g += __shfl_xor_sync(0xffffffffu, g, off);
    if (lane == 0) sAux[wid] = g;
    __syncthreads();
    if (j == 0) sGold = sAux[0] + sAux[1];

    // ---------------- Texp column j -> 32 packed f32x2 registers ------------
    unsigned long long tcp[CRF_T / 2];
    #pragma unroll
    for (int k = 0; k < CRF_T / 2; k++) {
        float a = ex2f(trans[(2 * k)     * CRF_T + j] * LOG2E);
        float c = ex2f(trans[(2 * k + 1) * CRF_T + j] * LOG2E);
        tcp[k] = pack2(a, c);
    }

    const float* ej = ebase + j;                 // emissions for state j
    float score = ej[0] * mb[0];

    // 4-deep prefetch pipeline over emissions / mask
    float pe[4], pm[4];
    #pragma unroll
    for (int p = 0; p < 4; p++) {
        int s = 1 + p;
        pe[p] = (s < CRF_S) ? ej[(size_t)s * CRF_T] : 0.f;
        pm[p] = (s < CRF_S) ? mb[s] : 0.f;
    }

    #pragma unroll 4
    for (int s = 1; s < CRF_S; s++) {
        int   p   = (s - 1) & 3;
        float emt = pe[p];
        float mk  = pm[p];
        int   sn  = s + 4;
        if (sn < CRF_S) { pe[p] = ej[(size_t)sn * CRF_T]; pm[p] = mb[sn]; }

        // ---- block max of score ----
        float m = score;
        #pragma unroll
        for (int off = 16; off; off >>= 1)
            m = fmaxf(m, __shfl_xor_sync(0xffffffffu, m, off));
        if (lane == 0) sred[wid] = m;
        __syncthreads();                 // (also fences prior-iter sE reads)
        m = fmaxf(sred[0], sred[1]);

        // ---- E[j] = exp(score - m) ----
        sE[j] = ex2f((score - m) * LOG2E);
        __syncthreads();

        // ---- dot: sum_i E[i] * Texp[i][j], packed f32x2 MACs ----
        unsigned long long acc0 = 0ull, acc1 = 0ull;
        const float4* sE4 = reinterpret_cast<const float4*>(sE);
        #pragma unroll
        for (int k = 0; k < CRF_T / 4; k++) {
            float4 e = sE4[k];
            acc0 = ffma2(pack2(e.x, e.y), tcp[2 * k],     acc0);
            acc1 = ffma2(pack2(e.z, e.w), tcp[2 * k + 1], acc1);
        }
        float a0x, a0y, a1x, a1y;
        unpack2(acc0, a0x, a0y);
        unpack2(acc1, a1x, a1y);
        float ssum = (a0x + a1x) + (a0y + a1y);

        // score = m + log(ssum) + emit * mask
        score = fmaf(lg2f(ssum), LN2, m) + emt * mk;
    }

    // ---------------- Final logsumexp over states ----------------
    float m = score;
    #pragma unroll
    for (int off = 16; off; off >>= 1)
        m = fmaxf(m, __shfl_xor_sync(0xffffffffu, m, off));
    if (lane == 0) sred[wid] = m;
    __syncthreads();
    m = fmaxf(sred[0], sred[1]);

    float e = ex2f((score - m) * LOG2E);
    #pragma unroll
    for (int off = 16; off; off >>= 1)
        e += __shfl_xor_sync(0xffffffffu, e, off);
    if (lane == 0) sAux[wid] = e;
    __syncthreads();

    if (j == 0) {
        float fwd = fmaf(lg2f(sAux[0] + sAux[1]), LN2, m);
        g_partial[b] = fwd - sGold;
    }
}

__global__ __launch_bounds__(CRF_B)
void crf_reduce(float* __restrict__ out)
{
    __shared__ float s[CRF_B];
    int t = threadIdx.x;
    s[t] = g_partial[t];
    __syncthreads();
    #pragma unroll
    for (int off = CRF_B / 2; off > 0; off >>= 1) {
        if (t < off) s[t] += s[t + off];
        __syncthreads();
    }
    if (t == 0) out[0] = s[0] * (1.0f / CRF_B);
}

extern "C" void kernel_launch(void* const* d_in, const int* in_sizes, int n_in,
                              void* d_out, int out_size)
{
    const float* emis  = (const float*)d_in[0];
    const int*   tags  = (const int*)  d_in[1];
    const float* mask  = (const float*)d_in[2];
    const float* trans = (const float*)d_in[3];

    crf_main<<<CRF_B, CRF_T>>>(emis, tags, mask, trans);
    crf_reduce<<<1, CRF_B>>>((float*)d_out);
}

// round 2
// speedup vs baseline: 1.1743x; 1.1743x over previous
#include <cuda_runtime.h>
#include <cstdint>

#define CRF_B 512
#define CRF_S 1024
#define CRF_T 64

__device__ float g_partial[CRF_B];

__device__ __forceinline__ float ex2f(float x) {
    float r; asm("ex2.approx.f32 %0, %1;" : "=f"(r) : "f"(x)); return r;
}
__device__ __forceinline__ float lg2f(float x) {
    float r; asm("lg2.approx.f32 %0, %1;" : "=f"(r) : "f"(x)); return r;
}
__device__ __forceinline__ unsigned long long pack2(float lo, float hi) {
    unsigned long long r;
    unsigned lo_u = __float_as_uint(lo), hi_u = __float_as_uint(hi);
    asm("mov.b64 %0, {%1, %2};" : "=l"(r) : "r"(lo_u), "r"(hi_u));
    return r;
}
__device__ __forceinline__ void unpack2(unsigned long long v, float& lo, float& hi) {
    unsigned lo_u, hi_u;
    asm("mov.b64 {%0, %1}, %2;" : "=r"(lo_u), "=r"(hi_u) : "l"(v));
    lo = __uint_as_float(lo_u); hi = __uint_as_float(hi_u);
}
// Packed dual-FMA: d.lo = a.lo*b.lo + c.lo ; d.hi = a.hi*b.hi + c.hi
__device__ __forceinline__ unsigned long long ffma2(unsigned long long a,
                                                    unsigned long long b,
                                                    unsigned long long c) {
    unsigned long long d;
    asm("fma.rn.f32x2 %0, %1, %2, %3;" : "=l"(d) : "l"(a), "l"(b), "l"(c));
    return d;
}

__global__ __launch_bounds__(CRF_T)
void crf_main(const float* __restrict__ emis,
              const int*   __restrict__ tags,
              const float* __restrict__ mask,
              const float* __restrict__ trans)
{
    const int b    = blockIdx.x;
    const int j    = threadIdx.x;       // state index 0..63
    const int lane = j & 31;
    const int wid  = j >> 5;

    // Double-buffered E array: one barrier per step is enough because
    // writes to buffer (s&1) at iter s+2 are separated from the readers
    // of iter s by the barrier of iter s+1.
    __shared__ __align__(16) float sE[2][CRF_T];
    __shared__ float sMref[2];          // lag-2 logsumexp reference (thread 0's score)
    __shared__ float sAux[2];
    __shared__ float sGold;

    const float LOG2E = 1.4426950408889634f;
    const float LN2   = 0.6931471805599453f;

    const float* mb    = mask + (size_t)b * CRF_S;
    const int*   tb    = tags + (size_t)b * CRF_S;
    const float* ebase = emis + (size_t)b * CRF_S * CRF_T;

    // ---------------- Gold score (gather pass, split over threads) ----------
    float g = 0.f;
    for (int s = j; s < CRF_S; s += CRF_T) {
        int   tg = tb[s];
        float ev = ebase[(size_t)s * CRF_T + tg];
        float term;
        if (s == 0) term = ev;
        else        term = trans[tg * CRF_T + tb[s - 1]] + ev;
        g += term * mb[s];
    }
    #pragma unroll
    for (int off = 16; off; off >>= 1)
        g += __shfl_xor_sync(0xffffffffu, g, off);
    if (lane == 0) sAux[wid] = g;
    __syncthreads();
    if (j == 0) sGold = sAux[0] + sAux[1];

    // ---------------- Texp column j -> 32 packed f32x2 registers ------------
    unsigned long long tcp[CRF_T / 2];
    #pragma unroll
    for (int k = 0; k < CRF_T / 2; k++) {
        float a = ex2f(trans[(2 * k)     * CRF_T + j] * LOG2E);
        float c = ex2f(trans[(2 * k + 1) * CRF_T + j] * LOG2E);
        tcp[k] = pack2(a, c);
    }

    const float* ej = ebase + j;                 // emissions for state j
    float score = ej[0] * mb[0];

    // One exact block max of the initial score (done once; afterwards the
    // reference is thread 0's score with lag 2 -- exact up to rounding since
    // the shift cancels: m + log(sum exp(x - m)).
    {
        float m = score;
        #pragma unroll
        for (int off = 16; off; off >>= 1)
            m = fmaxf(m, __shfl_xor_sync(0xffffffffu, m, off));
        if (lane == 0) sAux[wid] = m;
        __syncthreads();
        m = fmaxf(sAux[0], sAux[1]);
        if (j == 0) { sMref[0] = m; sMref[1] = m; }
        __syncthreads();
    }
    float mref      = sMref[0];   // reference used this iter
    float mref_next = sMref[0];   // reference for next iter

    // 4-deep prefetch pipeline over emissions / mask
    float pe[4], pm[4];
    #pragma unroll
    for (int p = 0; p < 4; p++) {
        int s = 1 + p;
        pe[p] = (s < CRF_S) ? ej[(size_t)s * CRF_T] : 0.f;
        pm[p] = (s < CRF_S) ? mb[s] : 0.f;
    }

    #pragma unroll 4
    for (int s = 1; s < CRF_S; s++) {
        const int buf = s & 1;
        int   p   = (s - 1) & 3;
        float emt = pe[p];
        float mk  = pm[p];
        int   sn  = s + 4;
        if (sn < CRF_S) { pe[p] = ej[(size_t)sn * CRF_T]; pm[p] = mb[sn]; }

        // ---- phase A: E[j] = exp(score - mref) ----
        sE[buf][j] = ex2f((score - mref) * LOG2E);
        __syncthreads();

        // ---- phase B ----
        // prefetch reference for iter s+1 (written at iter s-1; ordered by
        // the barrier above) -- latency hidden under the dot product
        float mref_pf = sMref[(s + 1) & 1];

        // dot: sum_i E[i] * Texp[i][j], packed f32x2 MACs, 4 accumulators
        unsigned long long acc0 = 0ull, acc1 = 0ull, acc2 = 0ull, acc3 = 0ull;
        const float4* sE4 = reinterpret_cast<const float4*>(sE[buf]);
        #pragma unroll
        for (int k = 0; k < CRF_T / 8; k++) {
            float4 e0 = sE4[2 * k];
            float4 e1 = sE4[2 * k + 1];
            acc0 = ffma2(pack2(e0.x, e0.y), tcp[4 * k],     acc0);
            acc1 = ffma2(pack2(e0.z, e0.w), tcp[4 * k + 1], acc1);
            acc2 = ffma2(pack2(e1.x, e1.y), tcp[4 * k + 2], acc2);
            acc3 = ffma2(pack2(e1.z, e1.w), tcp[4 * k + 3], acc3);
        }
        float a0x, a0y, a1x, a1y, a2x, a2y, a3x, a3y;
        unpack2(acc0, a0x, a0y);
        unpack2(acc1, a1x, a1y);
        unpack2(acc2, a2x, a2y);
        unpack2(acc3, a3x, a3y);
        float ssum = ((a0x + a1x) + (a0y + a1y)) + ((a2x + a3x) + (a2y + a3y));

        // score = mref + log(ssum) + emit * mask   (mref cancels exactly)
        score = fmaf(lg2f(ssum), LN2, mref) + emt * mk;

        // publish lag-2 reference for iter s+2
        if (j == 0) sMref[buf] = score;

        mref      = mref_next;
        mref_next = mref_pf;
    }

    // ---------------- Final logsumexp over states ----------------
    float m = score;
    #pragma unroll
    for (int off = 16; off; off >>= 1)
        m = fmaxf(m, __shfl_xor_sync(0xffffffffu, m, off));
    if (lane == 0) sAux[wid] = m;
    __syncthreads();
    m = fmaxf(sAux[0], sAux[1]);

    float e = ex2f((score - m) * LOG2E);
    #pragma unroll
    for (int off = 16; off; off >>= 1)
        e += __shfl_xor_sync(0xffffffffu, e, off);
    if (lane == 0) sAux[wid] = e;
    __syncthreads();

    if (j == 0) {
        float fwd = fmaf(lg2f(sAux[0] + sAux[1]), LN2, m);
        g_partial[b] = fwd - sGold;
    }
}

__global__ __launch_bounds__(CRF_B)
void crf_reduce(float* __restrict__ out)
{
    __shared__ float s[CRF_B];
    int t = threadIdx.x;
    s[t] = g_partial[t];
    __syncthreads();
    #pragma unroll
    for (int off = CRF_B / 2; off > 0; off >>= 1) {
        if (t < off) s[t] += s[t + off];
        __syncthreads();
    }
    if (t == 0) out[0] = s[0] * (1.0f / CRF_B);
}

extern "C" void kernel_launch(void* const* d_in, const int* in_sizes, int n_in,
                              void* d_out, int out_size)
{
    const float* emis  = (const float*)d_in[0];
    const int*   tags  = (const int*)  d_in[1];
    const float* mask  = (const float*)d_in[2];
    const float* trans = (const float*)d_in[3];

    crf_main<<<CRF_B, CRF_T>>>(emis, tags, mask, trans);
    crf_reduce<<<1, CRF_B>>>((float*)d_out);
}